// round 16
// baseline (speedup 1.0000x reference)
#include <cuda_runtime.h>
#include <cuda_fp16.h>
#include <cstdint>
#include <cstddef>

#define B_TOT 512
#define IC    1152
#define CD    160
#define KD    8
#define NC    10

// ---------------- scratch (device globals; no runtime allocation) ----------
__device__ __half g_uhat[(size_t)B_TOT * IC * CD];   // 188 MB, fp16
__device__ __half g_part[(size_t)144 * B_TOT * CD];  // 23.6 MB s1 partials
__device__ float  g_s[3 * B_TOT * CD];               // s1 | s2 | s3

// ---------------- f32x2 packed-math helpers (sm_103a) ----------------------
typedef unsigned long long ull;
__device__ __forceinline__ ull pack2(float lo, float hi) {
    ull r; asm("mov.b64 %0, {%1, %2};" : "=l"(r) : "f"(lo), "f"(hi)); return r;
}
__device__ __forceinline__ void unpack2(ull p, float& lo, float& hi) {
    asm("mov.b64 {%0, %1}, %2;" : "=f"(lo), "=f"(hi) : "l"(p));
}
__device__ __forceinline__ ull fma2(ull a, ull b, ull c) {
    ull d; asm("fma.rn.f32x2 %0, %1, %2, %3;" : "=l"(d) : "l"(a), "l"(b), "l"(c)); return d;
}

// ---------------- K1: u_hat + smem s1 partials ------------------------------
#define BT 32
#define IT 8
#define K1_THREADS 256
#define W_WORDS (IT * KD * CD)     // 10240
#define USTR 68
#define S1P_WORDS (BT * CD)        // 5120
#define K1_SMEM_FLOATS (W_WORDS + BT * USTR + S1P_WORDS)   // 17536 = 70.1 KB

__device__ __forceinline__ ull uhat_quad(const ull* wl, const ull* wh,
                                         float4 ua, float4 ub, ull& a23) {
    ull a01 = 0ull; a23 = 0ull; ull p;
    p = pack2(ua.x, ua.x); a01 = fma2(wl[0], p, a01); a23 = fma2(wh[0], p, a23);
    p = pack2(ua.y, ua.y); a01 = fma2(wl[1], p, a01); a23 = fma2(wh[1], p, a23);
    p = pack2(ua.z, ua.z); a01 = fma2(wl[2], p, a01); a23 = fma2(wh[2], p, a23);
    p = pack2(ua.w, ua.w); a01 = fma2(wl[3], p, a01); a23 = fma2(wh[3], p, a23);
    p = pack2(ub.x, ub.x); a01 = fma2(wl[4], p, a01); a23 = fma2(wh[4], p, a23);
    p = pack2(ub.y, ub.y); a01 = fma2(wl[5], p, a01); a23 = fma2(wh[5], p, a23);
    p = pack2(ub.z, ub.z); a01 = fma2(wl[6], p, a01); a23 = fma2(wh[6], p, a23);
    p = pack2(ub.w, ub.w); a01 = fma2(wl[7], p, a01); a23 = fma2(wh[7], p, a23);
    return a01;
}

__global__ void __launch_bounds__(K1_THREADS, 3)
k_uhat(const float* __restrict__ u, const float* __restrict__ W) {
    extern __shared__ float sm[];
    float* w_s  = sm;                       // [il][k][cd]
    float* u_s  = sm + W_WORDS;             // [bl][USTR]
    float* s1p  = sm + W_WORDS + BT * USTR; // [bl][cd]

    const int tid = threadIdx.x;
    const int b0  = blockIdx.x * BT;
    const int i0  = blockIdx.y * IT;

    for (int idx = tid; idx < S1P_WORDS; idx += K1_THREADS) s1p[idx] = 0.f;
    for (int idx = tid; idx < BT * IT * KD; idx += K1_THREADS) {
        const int bl = idx >> 6, r = idx & 63;
        u_s[bl * USTR + r] = u[(size_t)(b0 + bl) * (IC * KD) + (size_t)i0 * KD + r];
    }
    for (int row = tid; row < IT * CD; row += K1_THREADS) {
        const int il = row / CD, cd = row - il * CD;
        const float4 wa = *(const float4*)&W[((size_t)(i0 + il) * CD + cd) * KD];
        const float4 wb = *(const float4*)&W[((size_t)(i0 + il) * CD + cd) * KD + 4];
        float* dst = &w_s[il * (KD * CD) + cd];
        dst[0*CD] = wa.x; dst[1*CD] = wa.y; dst[2*CD] = wa.z; dst[3*CD] = wa.w;
        dst[4*CD] = wb.x; dst[5*CD] = wb.y; dst[6*CD] = wb.z; dst[7*CD] = wb.w;
    }
    __syncthreads();

    const int wid = tid >> 5, lane = tid & 31;
    const int il = wid, ig = i0 + il;
    const float* wrow = &w_s[il * (KD * CD)];

    // round 0: cd = lane*4 (0..127); loop all 32 bl -> coalesced 256B stores
    {
        const int cd0 = lane * 4;
        ull wl[8], wh[8];
#pragma unroll
        for (int k = 0; k < 8; k++) {
            const float4 wv = *(const float4*)&wrow[k * CD + cd0];
            wl[k] = pack2(wv.x, wv.y); wh[k] = pack2(wv.z, wv.w);
        }
#pragma unroll 4
        for (int bl = 0; bl < BT; bl++) {
            const float4 ua = *(const float4*)&u_s[bl * USTR + il * KD];
            const float4 ub = *(const float4*)&u_s[bl * USTR + il * KD + 4];
            ull a23; const ull a01 = uhat_quad(wl, wh, ua, ub, a23);
            float f0, f1, f2, f3;
            unpack2(a01, f0, f1); unpack2(a23, f2, f3);
            __half2 pa = __floats2half2_rn(f0, f1);
            __half2 pb = __floats2half2_rn(f2, f3);
            const ull payload = ((ull)*reinterpret_cast<unsigned*>(&pb) << 32)
                              |  (ull)*reinterpret_cast<unsigned*>(&pa);
            *reinterpret_cast<ull*>(
                &g_uhat[((size_t)(b0 + bl) * IC + ig) * CD + cd0]) = payload;
            float* sp = &s1p[bl * CD + cd0];
            atomicAdd(&sp[0], f0); atomicAdd(&sp[1], f1);
            atomicAdd(&sp[2], f2); atomicAdd(&sp[3], f3);
        }
    }
    // round 1: tail cd 128..159, 4 bl per step
    {
        const int bsub = lane >> 3, cq = lane & 7;
        const int cd0 = 128 + cq * 4;
        ull wl[8], wh[8];
#pragma unroll
        for (int k = 0; k < 8; k++) {
            const float4 wv = *(const float4*)&wrow[k * CD + cd0];
            wl[k] = pack2(wv.x, wv.y); wh[k] = pack2(wv.z, wv.w);
        }
#pragma unroll 2
        for (int st = 0; st < 8; st++) {
            const int bl = st * 4 + bsub;
            const float4 ua = *(const float4*)&u_s[bl * USTR + il * KD];
            const float4 ub = *(const float4*)&u_s[bl * USTR + il * KD + 4];
            ull a23; const ull a01 = uhat_quad(wl, wh, ua, ub, a23);
            float f0, f1, f2, f3;
            unpack2(a01, f0, f1); unpack2(a23, f2, f3);
            __half2 pa = __floats2half2_rn(f0, f1);
            __half2 pb = __floats2half2_rn(f2, f3);
            const ull payload = ((ull)*reinterpret_cast<unsigned*>(&pb) << 32)
                              |  (ull)*reinterpret_cast<unsigned*>(&pa);
            *reinterpret_cast<ull*>(
                &g_uhat[((size_t)(b0 + bl) * IC + ig) * CD + cd0]) = payload;
            float* sp = &s1p[bl * CD + cd0];
            atomicAdd(&sp[0], f0); atomicAdd(&sp[1], f1);
            atomicAdd(&sp[2], f2); atomicAdd(&sp[3], f3);
        }
    }
    // write block's s1 partial (fp16, non-atomic) to its slot
    __syncthreads();
    __half* part = &g_part[((size_t)blockIdx.y * B_TOT + b0) * CD];
    for (int idx = tid; idx < S1P_WORDS; idx += K1_THREADS)
        part[idx] = __float2half(s1p[idx]);
}

// ---------------- k_sum2: reduce 144 partial slots -> s1 --------------------
__global__ void __launch_bounds__(CD)
k_sum2(float* __restrict__ s1) {
    const int b = blockIdx.x;
    const int cd = threadIdx.x;
    const __half* p = &g_part[(size_t)b * CD + cd];
    float acc = 0.f;
#pragma unroll 8
    for (int y = 0; y < 144; y++)
        acc += __half2float(p[(size_t)y * B_TOT * CD]);
    s1[(size_t)b * CD + cd] = acc;
}

// ---------------- final squash ----------------------------------------------
__global__ void k_squash(const float* __restrict__ s, float* __restrict__ v) {
    const int idx = blockIdx.x * blockDim.x + threadIdx.x;
    if (idx >= B_TOT * NC) return;
    float vals[16];
    const float4* s4 = (const float4*)(s + (size_t)idx * 16);
    float n2 = 0.f;
#pragma unroll
    for (int q = 0; q < 4; q++) {
        float4 t = s4[q];
        vals[4*q+0] = t.x; vals[4*q+1] = t.y; vals[4*q+2] = t.z; vals[4*q+3] = t.w;
        n2 += t.x*t.x + t.y*t.y + t.z*t.z + t.w*t.w;
    }
    const float f = (n2 / (1.f + n2)) / (sqrtf(n2) + 1e-8f);
    float4* v4 = (float4*)(v + (size_t)idx * 16);
#pragma unroll
    for (int q = 0; q < 4; q++)
        v4[q] = make_float4(f*vals[4*q], f*vals[4*q+1], f*vals[4*q+2], f*vals[4*q+3]);
}

// ---------------- routing pass (EXACT R13 champion body) --------------------
__device__ __forceinline__ float ex2a(float x) { float y; asm("ex2.approx.f32 %0, %1;" : "=f"(y) : "f"(x)); return y; }
__device__ __forceinline__ float rcpa(float x) { float y; asm("rcp.approx.f32 %0, %1;" : "=f"(y) : "f"(x)); return y; }

#define NSPL 4
#define RT_THREADS 256

template <int MODE>   // 1: v1 only, 2: v1+v2 combined
__global__ void __launch_bounds__(RT_THREADS)
k_route(const float* __restrict__ s_in1, const float* __restrict__ s_in2,
        float* __restrict__ s_out) {
    __shared__ float4 vcs[40];
    __shared__ float  ssum[CD];

    const int b      = blockIdx.x;
    const int isplit = blockIdx.y;
    const int tid  = threadIdx.x;
    const int warp = tid >> 5, lane = tid & 31;
    const int grp = lane >> 3, sub = lane & 7;

    if (tid < CD) ssum[tid] = 0.f;

    if (tid < 10) {
        float vc[16]; float n2 = 0.f;
#pragma unroll
        for (int d = 0; d < 16; d++) {
            vc[d] = s_in1[(size_t)b * CD + tid * 16 + d] * 0.1f;
            n2 += vc[d] * vc[d];
        }
        const float fa = (n2 / (1.f + n2)) / (sqrtf(n2) + 1e-8f);
#pragma unroll
        for (int d = 0; d < 16; d++) vc[d] *= fa;
        if (MODE == 2) {
            float vb[16]; float m2 = 0.f;
#pragma unroll
            for (int d = 0; d < 16; d++) {
                vb[d] = s_in2[(size_t)b * CD + tid * 16 + d];
                m2 += vb[d] * vb[d];
            }
            const float fb = (m2 / (1.f + m2)) / (sqrtf(m2) + 1e-8f);
#pragma unroll
            for (int d = 0; d < 16; d++) vc[d] += fb * vb[d];
        }
#pragma unroll
        for (int q = 0; q < 4; q++)
            vcs[tid * 4 + q] = make_float4(vc[4*q], vc[4*q+1], vc[4*q+2], vc[4*q+3]);
    }
    __syncthreads();

    const uint2* uh_2 = (const uint2*)g_uhat;

    float4 vr[5];
#pragma unroll
    for (int j = 0; j < 5; j++) vr[j] = vcs[sub + 8 * j];

    float4 sacc[5];
#pragma unroll
    for (int j = 0; j < 5; j++) sacc[j] = make_float4(0.f, 0.f, 0.f, 0.f);

    const int iper = IC / NSPL;          // 288;  9 rounds of 32 i
#pragma unroll 3
    for (int t = 0; t < iper / 32; t++) {
        const int i = isplit * iper + t * 32 + warp * 4 + grp;
        const size_t base = (size_t)(b * IC + i) * 40;
        uint2 q[5];
#pragma unroll
        for (int j = 0; j < 5; j++) q[j] = __ldcs(&uh_2[base + sub + 8 * j]);
        float4 uh[5];
        float e[5]; float esum = 0.f;
#pragma unroll
        for (int j = 0; j < 5; j++) {
            float2 f0 = __half22float2(*reinterpret_cast<const __half2*>(&q[j].x));
            float2 f1 = __half22float2(*reinterpret_cast<const __half2*>(&q[j].y));
            uh[j] = make_float4(f0.x, f0.y, f1.x, f1.y);
            float d = uh[j].x * vr[j].x + uh[j].y * vr[j].y
                    + uh[j].z * vr[j].z + uh[j].w * vr[j].w;
            d += __shfl_xor_sync(0xffffffffu, d, 1);
            d += __shfl_xor_sync(0xffffffffu, d, 2);
            e[j] = ex2a(d * 1.4426950408889634f);
            esum += e[j];
        }
        const float tot = esum + __shfl_xor_sync(0xffffffffu, esum, 4);
        const float r = rcpa(tot);
#pragma unroll
        for (int j = 0; j < 5; j++) {
            const float cw = e[j] * r;
            sacc[j].x += cw * uh[j].x; sacc[j].y += cw * uh[j].y;
            sacc[j].z += cw * uh[j].z; sacc[j].w += cw * uh[j].w;
        }
    }

#pragma unroll
    for (int j = 0; j < 5; j++) {
        sacc[j].x += __shfl_xor_sync(0xffffffffu, sacc[j].x, 8);
        sacc[j].x += __shfl_xor_sync(0xffffffffu, sacc[j].x, 16);
        sacc[j].y += __shfl_xor_sync(0xffffffffu, sacc[j].y, 8);
        sacc[j].y += __shfl_xor_sync(0xffffffffu, sacc[j].y, 16);
        sacc[j].z += __shfl_xor_sync(0xffffffffu, sacc[j].z, 8);
        sacc[j].z += __shfl_xor_sync(0xffffffffu, sacc[j].z, 16);
        sacc[j].w += __shfl_xor_sync(0xffffffffu, sacc[j].w, 8);
        sacc[j].w += __shfl_xor_sync(0xffffffffu, sacc[j].w, 16);
    }
    if (grp == 0) {
#pragma unroll
        for (int j = 0; j < 5; j++) {
            const int cdb = 4 * (sub + 8 * j);
            atomicAdd(&ssum[cdb + 0], sacc[j].x);
            atomicAdd(&ssum[cdb + 1], sacc[j].y);
            atomicAdd(&ssum[cdb + 2], sacc[j].z);
            atomicAdd(&ssum[cdb + 3], sacc[j].w);
        }
    }
    __syncthreads();
    if (tid < CD)
        atomicAdd(&s_out[(size_t)b * CD + tid], ssum[tid]);
}

// ---------------- launch -----------------------------------------------------
extern "C" void kernel_launch(void* const* d_in, const int* in_sizes, int n_in,
                              void* d_out, int out_size) {
    const float* u = (const float*)d_in[0];
    const float* W = (const float*)d_in[1];
    if (n_in >= 2 && in_sizes[0] == IC * CD * KD) {   // swap safety
        const float* t = u; u = W; W = t;
    }

    cudaFuncSetAttribute(k_uhat, cudaFuncAttributeMaxDynamicSharedMemorySize,
                         K1_SMEM_FLOATS * (int)sizeof(float));

    void* ps;
    cudaGetSymbolAddress(&ps, g_s);
    float* s1 = (float*)ps;
    float* s2 = s1 + B_TOT * CD;
    float* s3 = s2 + B_TOT * CD;

    cudaMemsetAsync(s2, 0, 2 * B_TOT * CD * sizeof(float), 0);

    // 1) u_hat (fp16) + per-block s1 partials (no atomics to DRAM)
    k_uhat<<<dim3(B_TOT / BT, IC / IT), K1_THREADS,
             K1_SMEM_FLOATS * sizeof(float)>>>(u, W);
    // 2) s1 = reduce 144 partial slots (23.6 MB, not 188 MB)
    k_sum2<<<B_TOT, CD>>>(s1);
    // 3) iter-1: v1 = squash(0.1*s1); s2
    k_route<1><<<dim3(B_TOT, NSPL), RT_THREADS>>>(s1, s1, s2);
    // 4) iter-2: vc = v1 + v2; s3
    k_route<2><<<dim3(B_TOT, NSPL), RT_THREADS>>>(s1, s2, s3);
    // 5) output v = squash(s3)
    const int sq_blocks = (B_TOT * NC + 255) / 256;
    k_squash<<<sq_blocks, 256>>>(s3, (float*)d_out);
}

// round 17
// speedup vs baseline: 1.6063x; 1.6063x over previous
#include <cuda_runtime.h>
#include <cuda_fp16.h>
#include <cstdint>
#include <cstddef>

#define B_TOT 512
#define BH    256              // half of batch for the 2-stream pipeline
#define IC    1152
#define CD    160
#define KD    8
#define NC    10

// ---------------- scratch (device globals; no runtime allocation) ----------
__device__ __half g_uhat[(size_t)B_TOT * IC * CD];   // 188 MB, fp16
__device__ float  g_s[3 * B_TOT * CD];               // s1 | s2 | s3

// ---------------- f32x2 packed-math helpers (sm_103a) ----------------------
typedef unsigned long long ull;
__device__ __forceinline__ ull pack2(float lo, float hi) {
    ull r; asm("mov.b64 %0, {%1, %2};" : "=l"(r) : "f"(lo), "f"(hi)); return r;
}
__device__ __forceinline__ void unpack2(ull p, float& lo, float& hi) {
    asm("mov.b64 {%0, %1}, %2;" : "=f"(lo), "=f"(hi) : "l"(p));
}
__device__ __forceinline__ ull fma2(ull a, ull b, ull c) {
    ull d; asm("fma.rn.f32x2 %0, %1, %2, %3;" : "=l"(d) : "l"(a), "l"(b), "l"(c)); return d;
}

// ---------------- K1: u_hat, coalesced stores, w-in-regs (R13 champion) -----
#define BT 32
#define IT 8
#define K1_THREADS 256
#define W_WORDS (IT * KD * CD)     // 10240
#define USTR 68
#define K1_SMEM_FLOATS (W_WORDS + BT * USTR)   // 12416 words = 49.7 KB

__device__ __forceinline__ ull uhat_quad(const ull* wl, const ull* wh,
                                         float4 ua, float4 ub, ull& a23) {
    ull a01 = 0ull; a23 = 0ull; ull p;
    p = pack2(ua.x, ua.x); a01 = fma2(wl[0], p, a01); a23 = fma2(wh[0], p, a23);
    p = pack2(ua.y, ua.y); a01 = fma2(wl[1], p, a01); a23 = fma2(wh[1], p, a23);
    p = pack2(ua.z, ua.z); a01 = fma2(wl[2], p, a01); a23 = fma2(wh[2], p, a23);
    p = pack2(ua.w, ua.w); a01 = fma2(wl[3], p, a01); a23 = fma2(wh[3], p, a23);
    p = pack2(ub.x, ub.x); a01 = fma2(wl[4], p, a01); a23 = fma2(wh[4], p, a23);
    p = pack2(ub.y, ub.y); a01 = fma2(wl[5], p, a01); a23 = fma2(wh[5], p, a23);
    p = pack2(ub.z, ub.z); a01 = fma2(wl[6], p, a01); a23 = fma2(wh[6], p, a23);
    p = pack2(ub.w, ub.w); a01 = fma2(wl[7], p, a01); a23 = fma2(wh[7], p, a23);
    return a01;
}
__device__ __forceinline__ ull to_payload(ull a01, ull a23) {
    float f0, f1, f2, f3;
    unpack2(a01, f0, f1); unpack2(a23, f2, f3);
    __half2 pa = __floats2half2_rn(f0, f1);
    __half2 pb = __floats2half2_rn(f2, f3);
    return ((ull)*reinterpret_cast<unsigned*>(&pb) << 32)
         |  (ull)*reinterpret_cast<unsigned*>(&pa);
}

__global__ void __launch_bounds__(K1_THREADS, 3)
k_uhat(const float* __restrict__ u, const float* __restrict__ W, int bbase) {
    extern __shared__ float sm[];
    float* w_s = sm;                 // [il][k][cd]
    float* u_s = sm + W_WORDS;       // [bl][USTR]

    const int tid = threadIdx.x;
    const int b0  = bbase + blockIdx.x * BT;
    const int i0  = blockIdx.y * IT;

    for (int idx = tid; idx < BT * IT * KD; idx += K1_THREADS) {
        const int bl = idx >> 6, r = idx & 63;
        u_s[bl * USTR + r] = u[(size_t)(b0 + bl) * (IC * KD) + (size_t)i0 * KD + r];
    }
    for (int row = tid; row < IT * CD; row += K1_THREADS) {
        const int il = row / CD, cd = row - il * CD;
        const float4 wa = *(const float4*)&W[((size_t)(i0 + il) * CD + cd) * KD];
        const float4 wb = *(const float4*)&W[((size_t)(i0 + il) * CD + cd) * KD + 4];
        float* dst = &w_s[il * (KD * CD) + cd];
        dst[0*CD] = wa.x; dst[1*CD] = wa.y; dst[2*CD] = wa.z; dst[3*CD] = wa.w;
        dst[4*CD] = wb.x; dst[5*CD] = wb.y; dst[6*CD] = wb.z; dst[7*CD] = wb.w;
    }
    __syncthreads();

    const int wid = tid >> 5, lane = tid & 31;
    const int il = wid, ig = i0 + il;
    const float* wrow = &w_s[il * (KD * CD)];

    // round 0: cd = lane*4 (0..127); loop all 32 bl -> coalesced 256B stores
    {
        const int cd0 = lane * 4;
        ull wl[8], wh[8];
#pragma unroll
        for (int k = 0; k < 8; k++) {
            const float4 wv = *(const float4*)&wrow[k * CD + cd0];
            wl[k] = pack2(wv.x, wv.y); wh[k] = pack2(wv.z, wv.w);
        }
#pragma unroll 4
        for (int bl = 0; bl < BT; bl++) {
            const float4 ua = *(const float4*)&u_s[bl * USTR + il * KD];
            const float4 ub = *(const float4*)&u_s[bl * USTR + il * KD + 4];
            ull a23; const ull a01 = uhat_quad(wl, wh, ua, ub, a23);
            *reinterpret_cast<ull*>(
                &g_uhat[((size_t)(b0 + bl) * IC + ig) * CD + cd0]) = to_payload(a01, a23);
        }
    }
    // round 1: tail cd 128..159, 4 bl per step
    {
        const int bsub = lane >> 3, cq = lane & 7;
        const int cd0 = 128 + cq * 4;
        ull wl[8], wh[8];
#pragma unroll
        for (int k = 0; k < 8; k++) {
            const float4 wv = *(const float4*)&wrow[k * CD + cd0];
            wl[k] = pack2(wv.x, wv.y); wh[k] = pack2(wv.z, wv.w);
        }
#pragma unroll 2
        for (int st = 0; st < 8; st++) {
            const int bl = st * 4 + bsub;
            const float4 ua = *(const float4*)&u_s[bl * USTR + il * KD];
            const float4 ub = *(const float4*)&u_s[bl * USTR + il * KD + 4];
            ull a23; const ull a01 = uhat_quad(wl, wh, ua, ub, a23);
            *reinterpret_cast<ull*>(
                &g_uhat[((size_t)(b0 + bl) * IC + ig) * CD + cd0]) = to_payload(a01, a23);
        }
    }
}

// ---------------- k_sum: s1[b] += partial sums over i (4-way i-split) -------
#define SSPL 4
__global__ void __launch_bounds__(256)
k_sum(float* __restrict__ s1, int bbase) {
    __shared__ float part[6][CD];
    const int bg = bbase + blockIdx.x;
    const int isplit = blockIdx.y;
    const int t = threadIdx.x;
    const int iper = IC / SSPL;          // 288
    if (t < 240) {
        const int q = t % 40, is = t / 40;
        const uint2* base = (const uint2*)g_uhat + (size_t)bg * IC * 40 + q;
        float a0 = 0.f, a1 = 0.f, a2 = 0.f, a3 = 0.f;
#pragma unroll 4
        for (int k = is; k < iper; k += 6) {
            const uint2 v = __ldcs(&base[(size_t)(isplit * iper + k) * 40]);
            const float2 f0 = __half22float2(*reinterpret_cast<const __half2*>(&v.x));
            const float2 f1 = __half22float2(*reinterpret_cast<const __half2*>(&v.y));
            a0 += f0.x; a1 += f0.y; a2 += f1.x; a3 += f1.y;
        }
        part[is][q * 4 + 0] = a0; part[is][q * 4 + 1] = a1;
        part[is][q * 4 + 2] = a2; part[is][q * 4 + 3] = a3;
    }
    __syncthreads();
    if (t < CD) {
        float s = part[0][t] + part[1][t] + part[2][t]
                + part[3][t] + part[4][t] + part[5][t];
        atomicAdd(&s1[(size_t)bg * CD + t], s);
    }
}

// ---------------- final squash ----------------------------------------------
__global__ void k_squash(const float* __restrict__ s, float* __restrict__ v) {
    const int idx = blockIdx.x * blockDim.x + threadIdx.x;
    if (idx >= B_TOT * NC) return;
    float vals[16];
    const float4* s4 = (const float4*)(s + (size_t)idx * 16);
    float n2 = 0.f;
#pragma unroll
    for (int q = 0; q < 4; q++) {
        float4 t = s4[q];
        vals[4*q+0] = t.x; vals[4*q+1] = t.y; vals[4*q+2] = t.z; vals[4*q+3] = t.w;
        n2 += t.x*t.x + t.y*t.y + t.z*t.z + t.w*t.w;
    }
    const float f = (n2 / (1.f + n2)) / (sqrtf(n2) + 1e-8f);
    float4* v4 = (float4*)(v + (size_t)idx * 16);
#pragma unroll
    for (int q = 0; q < 4; q++)
        v4[q] = make_float4(f*vals[4*q], f*vals[4*q+1], f*vals[4*q+2], f*vals[4*q+3]);
}

// ---------------- routing pass (EXACT R13 champion body) --------------------
__device__ __forceinline__ float ex2a(float x) { float y; asm("ex2.approx.f32 %0, %1;" : "=f"(y) : "f"(x)); return y; }
__device__ __forceinline__ float rcpa(float x) { float y; asm("rcp.approx.f32 %0, %1;" : "=f"(y) : "f"(x)); return y; }

#define NSPL 4
#define RT_THREADS 256

template <int MODE>   // 1: v1 only, 2: v1+v2 combined
__global__ void __launch_bounds__(RT_THREADS)
k_route(const float* __restrict__ s_in1, const float* __restrict__ s_in2,
        float* __restrict__ s_out, int bbase) {
    __shared__ float4 vcs[40];
    __shared__ float  ssum[CD];

    const int b      = bbase + blockIdx.x;
    const int isplit = blockIdx.y;
    const int tid  = threadIdx.x;
    const int warp = tid >> 5, lane = tid & 31;
    const int grp = lane >> 3, sub = lane & 7;

    if (tid < CD) ssum[tid] = 0.f;

    if (tid < 10) {
        float vc[16]; float n2 = 0.f;
#pragma unroll
        for (int d = 0; d < 16; d++) {
            vc[d] = s_in1[(size_t)b * CD + tid * 16 + d] * 0.1f;
            n2 += vc[d] * vc[d];
        }
        const float fa = (n2 / (1.f + n2)) / (sqrtf(n2) + 1e-8f);
#pragma unroll
        for (int d = 0; d < 16; d++) vc[d] *= fa;
        if (MODE == 2) {
            float vb[16]; float m2 = 0.f;
#pragma unroll
            for (int d = 0; d < 16; d++) {
                vb[d] = s_in2[(size_t)b * CD + tid * 16 + d];
                m2 += vb[d] * vb[d];
            }
            const float fb = (m2 / (1.f + m2)) / (sqrtf(m2) + 1e-8f);
#pragma unroll
            for (int d = 0; d < 16; d++) vc[d] += fb * vb[d];
        }
#pragma unroll
        for (int q = 0; q < 4; q++)
            vcs[tid * 4 + q] = make_float4(vc[4*q], vc[4*q+1], vc[4*q+2], vc[4*q+3]);
    }
    __syncthreads();

    const uint2* uh_2 = (const uint2*)g_uhat;

    float4 vr[5];
#pragma unroll
    for (int j = 0; j < 5; j++) vr[j] = vcs[sub + 8 * j];

    float4 sacc[5];
#pragma unroll
    for (int j = 0; j < 5; j++) sacc[j] = make_float4(0.f, 0.f, 0.f, 0.f);

    const int iper = IC / NSPL;          // 288;  9 rounds of 32 i
#pragma unroll 3
    for (int t = 0; t < iper / 32; t++) {
        const int i = isplit * iper + t * 32 + warp * 4 + grp;
        const size_t base = (size_t)(b * IC + i) * 40;
        uint2 q[5];
#pragma unroll
        for (int j = 0; j < 5; j++) q[j] = __ldcs(&uh_2[base + sub + 8 * j]);
        float4 uh[5];
        float e[5]; float esum = 0.f;
#pragma unroll
        for (int j = 0; j < 5; j++) {
            float2 f0 = __half22float2(*reinterpret_cast<const __half2*>(&q[j].x));
            float2 f1 = __half22float2(*reinterpret_cast<const __half2*>(&q[j].y));
            uh[j] = make_float4(f0.x, f0.y, f1.x, f1.y);
            float d = uh[j].x * vr[j].x + uh[j].y * vr[j].y
                    + uh[j].z * vr[j].z + uh[j].w * vr[j].w;
            d += __shfl_xor_sync(0xffffffffu, d, 1);
            d += __shfl_xor_sync(0xffffffffu, d, 2);
            e[j] = ex2a(d * 1.4426950408889634f);
            esum += e[j];
        }
        const float tot = esum + __shfl_xor_sync(0xffffffffu, esum, 4);
        const float r = rcpa(tot);
#pragma unroll
        for (int j = 0; j < 5; j++) {
            const float cw = e[j] * r;
            sacc[j].x += cw * uh[j].x; sacc[j].y += cw * uh[j].y;
            sacc[j].z += cw * uh[j].z; sacc[j].w += cw * uh[j].w;
        }
    }

#pragma unroll
    for (int j = 0; j < 5; j++) {
        sacc[j].x += __shfl_xor_sync(0xffffffffu, sacc[j].x, 8);
        sacc[j].x += __shfl_xor_sync(0xffffffffu, sacc[j].x, 16);
        sacc[j].y += __shfl_xor_sync(0xffffffffu, sacc[j].y, 8);
        sacc[j].y += __shfl_xor_sync(0xffffffffu, sacc[j].y, 16);
        sacc[j].z += __shfl_xor_sync(0xffffffffu, sacc[j].z, 8);
        sacc[j].z += __shfl_xor_sync(0xffffffffu, sacc[j].z, 16);
        sacc[j].w += __shfl_xor_sync(0xffffffffu, sacc[j].w, 8);
        sacc[j].w += __shfl_xor_sync(0xffffffffu, sacc[j].w, 16);
    }
    if (grp == 0) {
#pragma unroll
        for (int j = 0; j < 5; j++) {
            const int cdb = 4 * (sub + 8 * j);
            atomicAdd(&ssum[cdb + 0], sacc[j].x);
            atomicAdd(&ssum[cdb + 1], sacc[j].y);
            atomicAdd(&ssum[cdb + 2], sacc[j].z);
            atomicAdd(&ssum[cdb + 3], sacc[j].w);
        }
    }
    __syncthreads();
    if (tid < CD)
        atomicAdd(&s_out[(size_t)b * CD + tid], ssum[tid]);
}

// ---------------- launch: 2-stream fork-join pipeline over b-halves ---------
extern "C" void kernel_launch(void* const* d_in, const int* in_sizes, int n_in,
                              void* d_out, int out_size) {
    const float* u = (const float*)d_in[0];
    const float* W = (const float*)d_in[1];
    if (n_in >= 2 && in_sizes[0] == IC * CD * KD) {   // swap safety
        const float* t = u; u = W; W = t;
    }

    // lazily created once on the (pre-capture) correctness call; reused after
    static cudaStream_t s2 = nullptr;
    static cudaEvent_t evA = nullptr, evD0 = nullptr;
    if (s2 == nullptr) {
        cudaStreamCreateWithFlags(&s2, cudaStreamNonBlocking);
        cudaEventCreateWithFlags(&evA, cudaEventDisableTiming);
        cudaEventCreateWithFlags(&evD0, cudaEventDisableTiming);
    }

    cudaFuncSetAttribute(k_uhat, cudaFuncAttributeMaxDynamicSharedMemorySize,
                         K1_SMEM_FLOATS * (int)sizeof(float));

    void* ps;
    cudaGetSymbolAddress(&ps, g_s);
    float* s1 = (float*)ps;
    float* sB = s1 + B_TOT * CD;
    float* sC = sB + B_TOT * CD;

    cudaMemsetAsync(ps, 0, 3 * B_TOT * CD * sizeof(float), 0);

    const dim3 gK(BH / BT, IC / IT);
    const dim3 gS(BH, SSPL);
    const dim3 gR(BH, NSPL);
    const int smem = K1_SMEM_FLOATS * sizeof(float);

    // main: K1 half0, then fork
    k_uhat<<<gK, K1_THREADS, smem, 0>>>(u, W, 0);
    cudaEventRecord(evA, 0);
    // main continues with half1 K1 + its routing chain
    k_uhat<<<gK, K1_THREADS, smem, 0>>>(u, W, BH);
    // s2: half0 routing chain, overlapped with main's K1(H1)
    cudaStreamWaitEvent(s2, evA, 0);
    k_sum<<<gS, 256, 0, s2>>>(s1, 0);
    k_route<1><<<gR, RT_THREADS, 0, s2>>>(s1, s1, sB, 0);
    k_route<2><<<gR, RT_THREADS, 0, s2>>>(s1, sB, sC, 0);
    cudaEventRecord(evD0, s2);
    // main: half1 chain
    k_sum<<<gS, 256, 0, 0>>>(s1, BH);
    k_route<1><<<gR, RT_THREADS, 0, 0>>>(s1, s1, sB, BH);
    k_route<2><<<gR, RT_THREADS, 0, 0>>>(s1, sB, sC, BH);
    // join and finish
    cudaStreamWaitEvent(0, evD0, 0);
    const int sq_blocks = (B_TOT * NC + 255) / 256;
    k_squash<<<sq_blocks, 256, 0, 0>>>(sC, (float*)d_out);
}